// round 13
// baseline (speedup 1.0000x reference)
#include <cuda_runtime.h>
#include <cuda_fp16.h>
#include <cstdint>

// ---------------------------------------------------------------------------
// Problem constants
// ---------------------------------------------------------------------------
#define BB 2
#define HH 16
#define SS 2048
#define DD 64
#define BH (BB*HH)              // 32
#define ROWS (BH*SS)            // 65536
#define TOT (ROWS*DD)           // 4194304

#define QT 128                  // q rows per CTA
#define KT 64                   // keys per tile
#define NT (SS/KT)              // 32 tiles

// smem row stride in halves: 88 (176 B) -> ldmatrix 8-row phases conflict-free
#define HSTRIDE 88
#define QBYTES  (QT*HSTRIDE*2)      // 22528
#define TBYTES  (KT*HSTRIDE*2)      // 11264
#define WBYTES  (64*HSTRIDE*2)      // 11264

#define SMEM_ATTN (QBYTES + 4*TBYTES)    // 67584 (Q + 2-deep K/V ring) -> 3 CTAs/SM
#define SMEM_PROJ (QBYTES + 3*WBYTES)    // 56320  (x + Wq/Wk/Wv)

// log2(e)/sqrt(64)  (folded into Q at projection time)
#define CEXP 0.18033688011112042f

// fp16 1.0 x2 (B-fragment of all-ones for row-sum MMA)
#define ONES2 0x3C003C00u

// Device scratch for projected Q, K, V (fp16; Q pre-scaled by CEXP)
__device__ __half g_Q[TOT];
__device__ __half g_K[TOT];
__device__ __half g_V[TOT];

// ---------------------------------------------------------------------------
// helpers
// ---------------------------------------------------------------------------
static __device__ __forceinline__ uint32_t smem_u32(const void* p) {
    uint32_t a;
    asm("{ .reg .u64 t; cvta.to.shared.u64 t, %1; cvt.u32.u64 %0, t; }"
        : "=r"(a) : "l"(p));
    return a;
}

static __device__ __forceinline__ void cpa16(uint32_t s, const void* g) {
    asm volatile("cp.async.ca.shared.global [%0], [%1], 16;"
                 :: "r"(s), "l"(g) : "memory");
}

static __device__ __forceinline__ uint32_t packh2(float lo, float hi) {
    __half2 h = __floats2half2_rn(lo, hi);
    return *reinterpret_cast<uint32_t*>(&h);
}

// 2-lane fp16 exp2 on the MUFU pipe (one op for two P values)
static __device__ __forceinline__ uint32_t ex2h2(uint32_t s) {
    uint32_t r;
    asm("ex2.approx.f16x2 %0, %1;" : "=r"(r) : "r"(s));
    return r;
}

#define LDSM_X4(r0, r1, r2, r3, addr) \
    asm volatile("ldmatrix.sync.aligned.m8n8.x4.shared.b16 {%0,%1,%2,%3}, [%4];" \
        : "=r"(r0), "=r"(r1), "=r"(r2), "=r"(r3) : "r"(addr))

#define LDSM_X4_T(r0, r1, r2, r3, addr) \
    asm volatile("ldmatrix.sync.aligned.m8n8.x4.trans.shared.b16 {%0,%1,%2,%3}, [%4];" \
        : "=r"(r0), "=r"(r1), "=r"(r2), "=r"(r3) : "r"(addr))

// c += A (16x16 f16, row) * B (16x8 f16, col), f32 accumulate
static __device__ __forceinline__ void mma16(float c[4], const uint32_t a[4],
                                             uint32_t b0, uint32_t b1) {
    asm volatile(
        "mma.sync.aligned.m16n8k16.row.col.f32.f16.f16.f32 "
        "{%0,%1,%2,%3}, {%4,%5,%6,%7}, {%8,%9}, {%0,%1,%2,%3};"
        : "+f"(c[0]), "+f"(c[1]), "+f"(c[2]), "+f"(c[3])
        : "r"(a[0]), "r"(a[1]), "r"(a[2]), "r"(a[3]), "r"(b0), "r"(b1));
}

// ---------------------------------------------------------------------------
// Kernel 1: fused QKV projection, full fp16 mma.m16n8k16 (proven round 10).
// ---------------------------------------------------------------------------
__global__ __launch_bounds__(128) void proj_f16(
    const float* __restrict__ x,
    const float* __restrict__ Wq, const float* __restrict__ bq,
    const float* __restrict__ Wk, const float* __restrict__ bk,
    const float* __restrict__ Wv, const float* __restrict__ bv)
{
    extern __shared__ char psm[];
    const uint32_t sX = smem_u32(psm);

    const int tid  = threadIdx.x;
    const int warp = tid >> 5;
    const int lane = tid & 31;
    const int mi   = lane >> 3;
    const int jj   = lane & 7;
    const int tig  = lane & 3;
    const int g    = lane >> 2;
    const int rcta = blockIdx.x * 128;

    // ---- stage x (128 x 64 f32 -> f16) ----
    #pragma unroll
    for (int p = 0; p < 16; ++p) {
        const int i = tid + p * 128;
        const int r = i >> 4, seg = i & 15;
        float4 v = *(const float4*)(x + (size_t)(rcta + r) * DD + seg * 4);
        uint2 h = make_uint2(packh2(v.x, v.y), packh2(v.z, v.w));
        *(uint2*)(psm + r * (HSTRIDE*2) + seg * 8) = h;
    }
    // ---- stage W matrices (64 x 64 f32 -> f16 each) ----
    {
        const float* Ws[3] = { Wq, Wk, Wv };
        #pragma unroll
        for (int mat = 0; mat < 3; ++mat) {
            char* wd = psm + QBYTES + mat * WBYTES;
            #pragma unroll
            for (int p = 0; p < 8; ++p) {
                const int i = tid + p * 128;
                const int r = i >> 4, seg = i & 15;
                float4 v = *(const float4*)(Ws[mat] + (size_t)r * DD + seg * 4);
                uint2 h = make_uint2(packh2(v.x, v.y), packh2(v.z, v.w));
                *(uint2*)(wd + r * (HSTRIDE*2) + seg * 8) = h;
            }
        }
    }
    __syncthreads();

    // ---- x A-fragments: 2 m-tiles x 4 k16-chunks ----
    uint32_t xa[2][4][4];
    #pragma unroll
    for (int m = 0; m < 2; ++m)
        #pragma unroll
        for (int kk = 0; kk < 4; ++kk) {
            const uint32_t a = sX +
                ((warp*32 + m*16 + (mi & 1)*8 + jj) * HSTRIDE + kk*16 + (mi >> 1)*8) * 2;
            LDSM_X4(xa[m][kk][0], xa[m][kk][1], xa[m][kk][2], xa[m][kk][3], a);
        }

    const float* bs[3] = { bq, bk, bv };
    __half* outs[3]    = { g_Q, g_K, g_V };

    #pragma unroll
    for (int mat = 0; mat < 3; ++mat) {
        const float* b = bs[mat];
        const uint32_t sW = sX + QBYTES + mat * WBYTES;

        float cacc[2][8][4];
        #pragma unroll
        for (int n = 0; n < 8; ++n) {
            const float b0 = b[n * 8 + 2 * tig];
            const float b1 = b[n * 8 + 2 * tig + 1];
            #pragma unroll
            for (int m = 0; m < 2; ++m) {
                cacc[m][n][0] = b0; cacc[m][n][1] = b1;
                cacc[m][n][2] = b0; cacc[m][n][3] = b1;
            }
        }

        #pragma unroll
        for (int n = 0; n < 8; n += 2) {
            uint32_t wb[2][4][2];
            #pragma unroll
            for (int nn = 0; nn < 2; ++nn)
                #pragma unroll
                for (int kp = 0; kp < 2; ++kp) {
                    const uint32_t a = sW +
                        (((n+nn)*8 + jj) * HSTRIDE + kp*32 + (mi & 1)*8 + (mi >> 1)*16) * 2;
                    LDSM_X4(wb[nn][2*kp][0], wb[nn][2*kp][1],
                            wb[nn][2*kp+1][0], wb[nn][2*kp+1][1], a);
                }
            #pragma unroll
            for (int kk = 0; kk < 4; ++kk)
                #pragma unroll
                for (int nn = 0; nn < 2; ++nn) {
                    mma16(cacc[0][n+nn], xa[0][kk], wb[nn][kk][0], wb[nn][kk][1]);
                    mma16(cacc[1][n+nn], xa[1][kk], wb[nn][kk][0], wb[nn][kk][1]);
                }
        }

        const float scale = (mat == 0) ? CEXP : 1.0f;
        __half* ob = outs[mat] + (size_t)rcta * DD;
        #pragma unroll
        for (int m = 0; m < 2; ++m) {
            const int r0 = warp * 32 + m * 16 + g;
            #pragma unroll
            for (int n = 0; n < 8; ++n) {
                const int c = n * 8 + 2 * tig;
                *(__half2*)(ob + (size_t)(r0    ) * DD + c) =
                    __floats2half2_rn(cacc[m][n][0] * scale, cacc[m][n][1] * scale);
                *(__half2*)(ob + (size_t)(r0 + 8) * DD + c) =
                    __floats2half2_rn(cacc[m][n][2] * scale, cacc[m][n][3] * scale);
            }
        }
    }
}

// ---------------------------------------------------------------------------
// Kernel 2: fp16 mma flash attention, no-max softmax.
// Round-11 shape (block 128, 2 m-tiles/warp for K/V fragment amortization)
// with: 2-deep K/V ring + per-tile {sync, prefetch(j+1), wait_group 1}
// (smem 67.6 KB -> 3 CTAs/SM), and per-n-pair exp/pack so only a 16-reg
// score sliver is live (fits the 170-reg 3-CTA ceiling; exp of pair p
// overlaps MMAs of pair p+1).
// ---------------------------------------------------------------------------
__global__ __launch_bounds__(128, 3) void attn_tc(float* __restrict__ out)
{
    extern __shared__ char smc[];
    const uint32_t sQ = smem_u32(smc);
    uint32_t bufK[2], bufV[2];
    #pragma unroll
    for (int i = 0; i < 2; ++i) {
        bufK[i] = sQ + QBYTES + (uint32_t)(2*i) * TBYTES;
        bufV[i] = bufK[i] + TBYTES;
    }

    const int tid  = threadIdx.x;
    const int warp = tid >> 5;
    const int lane = tid & 31;
    const int mi   = lane >> 3;
    const int jj   = lane & 7;
    const int g    = lane >> 2;
    const int tig  = lane & 3;
    const int bh   = blockIdx.y;
    const int q0   = blockIdx.x * QT;
    const size_t rowbase = (size_t)bh * SS;

    const __half* gQ = g_Q + (rowbase + q0) * DD;
    const __half* gK = g_K + rowbase * DD;
    const __half* gV = g_V + rowbase * DD;

    auto prefetch = [&](int j) {
        if (j < NT) {
            const __half* pk = gK + (size_t)j * KT * DD;
            const __half* pv = gV + (size_t)j * KT * DD;
            const uint32_t sk = bufK[j & 1];
            const uint32_t sv = bufV[j & 1];
            #pragma unroll
            for (int p = 0; p < 4; ++p) {
                const int i = tid + p * 128;
                const int r = i >> 3, seg = i & 7;
                const uint32_t so = (uint32_t)(r * (HSTRIDE*2) + seg * 16);
                cpa16(sk + so, pk + r * DD + seg * 8);
                cpa16(sv + so, pv + r * DD + seg * 8);
            }
        }
        asm volatile("cp.async.commit_group;" ::: "memory");
    };

    prefetch(0);

    // ---- stage Q tile ----
    #pragma unroll
    for (int p = 0; p < 8; ++p) {
        const int i = tid + p * 128;
        const int r = i >> 3, seg = i & 7;
        uint4 v = *(const uint4*)(gQ + r * DD + seg * 8);
        *(uint4*)(smc + r * (HSTRIDE*2) + seg * 16) = v;
    }
    __syncthreads();

    // ---- Q A-fragments ----
    uint32_t qf[2][4][4];
    #pragma unroll
    for (int m = 0; m < 2; ++m)
        #pragma unroll
        for (int kk = 0; kk < 4; ++kk) {
            const uint32_t a = sQ +
                ((warp*32 + m*16 + (mi & 1)*8 + jj) * HSTRIDE + kk*16 + (mi >> 1)*8) * 2;
            LDSM_X4(qf[m][kk][0], qf[m][kk][1], qf[m][kk][2], qf[m][kk][3], a);
        }

    float oacc[2][8][4];
    #pragma unroll
    for (int m = 0; m < 2; ++m)
        #pragma unroll
        for (int n = 0; n < 8; ++n)
            #pragma unroll
            for (int e = 0; e < 4; ++e) oacc[m][n][e] = 0.f;
    float lacc[2][4];
    #pragma unroll
    for (int m = 0; m < 2; ++m)
        #pragma unroll
        for (int e = 0; e < 4; ++e) lacc[m][e] = 0.f;

    for (int j = 0; j < NT; ++j) {
        __syncthreads();                     // tile j-1 readers done with its buffers
        prefetch(j + 1);                     // overwrite buffer (j+1)&1 (read at j-1)
        asm volatile("cp.async.wait_group 1;" ::: "memory");   // group j complete
        __syncthreads();                     // tile j visible to all warps

        const uint32_t K = bufK[j & 1];
        const uint32_t V = bufV[j & 1];

        // ---- S = Q K^T, exp+pack per n-pair (16-reg score sliver) ----
        uint32_t pa[2][4][4];
        #pragma unroll
        for (int n = 0; n < 8; n += 2) {
            uint32_t kb[2][4][2];
            #pragma unroll
            for (int nn = 0; nn < 2; ++nn)
                #pragma unroll
                for (int kp = 0; kp < 2; ++kp) {
                    const uint32_t a = K +
                        (((n+nn)*8 + jj) * HSTRIDE + kp*32 + (mi & 1)*8 + (mi >> 1)*16) * 2;
                    LDSM_X4(kb[nn][2*kp][0], kb[nn][2*kp][1],
                            kb[nn][2*kp+1][0], kb[nn][2*kp+1][1], a);
                }

            float sp[2][2][4];
            #pragma unroll
            for (int m = 0; m < 2; ++m)
                #pragma unroll
                for (int nn = 0; nn < 2; ++nn)
                    #pragma unroll
                    for (int e = 0; e < 4; ++e) sp[m][nn][e] = 0.f;

            #pragma unroll
            for (int kk = 0; kk < 4; ++kk)
                #pragma unroll
                for (int nn = 0; nn < 2; ++nn) {
                    mma16(sp[0][nn], qf[0][kk], kb[nn][kk][0], kb[nn][kk][1]);
                    mma16(sp[1][nn], qf[1][kk], kb[nn][kk][0], kb[nn][kk][1]);
                }

            const int pr = n >> 1;
            #pragma unroll
            for (int m = 0; m < 2; ++m) {
                pa[m][pr][0] = ex2h2(packh2(sp[m][0][0], sp[m][0][1]));
                pa[m][pr][1] = ex2h2(packh2(sp[m][0][2], sp[m][0][3]));
                pa[m][pr][2] = ex2h2(packh2(sp[m][1][0], sp[m][1][1]));
                pa[m][pr][3] = ex2h2(packh2(sp[m][1][2], sp[m][1][3]));
            }
        }

        // ---- row sums via all-ones B fragment ----
        #pragma unroll
        for (int m = 0; m < 2; ++m)
            #pragma unroll
            for (int kk = 0; kk < 4; ++kk)
                mma16(lacc[m], pa[m][kk], ONES2, ONES2);

        // ---- O += P V ----
        #pragma unroll
        for (int n = 0; n < 8; n += 2) {
            uint32_t vb[2][4][2];
            #pragma unroll
            for (int nn = 0; nn < 2; ++nn)
                #pragma unroll
                for (int kp = 0; kp < 2; ++kp) {
                    const uint32_t a = V +
                        ((kp*32 + (mi >> 1)*16 + (mi & 1)*8 + jj) * HSTRIDE + (n+nn)*8) * 2;
                    LDSM_X4_T(vb[nn][2*kp][0], vb[nn][2*kp][1],
                              vb[nn][2*kp+1][0], vb[nn][2*kp+1][1], a);
                }
            #pragma unroll
            for (int kk = 0; kk < 4; ++kk)
                #pragma unroll
                for (int nn = 0; nn < 2; ++nn) {
                    mma16(oacc[0][n+nn], pa[0][kk], vb[nn][kk][0], vb[nn][kk][1]);
                    mma16(oacc[1][n+nn], pa[1][kk], vb[nn][kk][0], vb[nn][kk][1]);
                }
        }
    }

    // ---- epilogue: normalize and store (lacc[m][0]=rows g, [2]=rows g+8) ----
    float inv[2][2];
    #pragma unroll
    for (int m = 0; m < 2; ++m) {
        inv[m][0] = 1.f / lacc[m][0];
        inv[m][1] = 1.f / lacc[m][2];
    }

    float* ob = out + (rowbase + q0 + warp * 32) * DD;
    #pragma unroll
    for (int m = 0; m < 2; ++m) {
        const int r0 = m * 16 + g;
        #pragma unroll
        for (int n = 0; n < 8; ++n) {
            const int c = n * 8 + 2 * tig;
            float2 v0 = make_float2(oacc[m][n][0] * inv[m][0], oacc[m][n][1] * inv[m][0]);
            *(float2*)(ob + r0 * DD + c) = v0;
            float2 v1 = make_float2(oacc[m][n][2] * inv[m][1], oacc[m][n][3] * inv[m][1]);
            *(float2*)(ob + (r0 + 8) * DD + c) = v1;
        }
    }
}

// ---------------------------------------------------------------------------
extern "C" void kernel_launch(void* const* d_in, const int* in_sizes, int n_in,
                              void* d_out, int out_size)
{
    const float* x  = (const float*)d_in[0];
    const float* Wq = (const float*)d_in[1];
    const float* bq = (const float*)d_in[2];
    const float* Wk = (const float*)d_in[3];
    const float* bk = (const float*)d_in[4];
    const float* Wv = (const float*)d_in[5];
    const float* bv = (const float*)d_in[6];
    float* out = (float*)d_out;

    static int configured = 0;
    if (!configured) {
        cudaFuncSetAttribute(attn_tc, cudaFuncAttributeMaxDynamicSharedMemorySize, SMEM_ATTN);
        cudaFuncSetAttribute(proj_f16, cudaFuncAttributeMaxDynamicSharedMemorySize, SMEM_PROJ);
        configured = 1;
    }

    proj_f16<<<ROWS / 128, 128, SMEM_PROJ>>>(x, Wq, bq, Wk, bk, Wv, bv);

    dim3 agrid(SS / QT, BH);
    attn_tc<<<agrid, 128, SMEM_ATTN>>>(out);
}

// round 14
// speedup vs baseline: 1.2091x; 1.2091x over previous
#include <cuda_runtime.h>
#include <cuda_fp16.h>
#include <cstdint>

// ---------------------------------------------------------------------------
// Problem constants
// ---------------------------------------------------------------------------
#define BB 2
#define HH 16
#define SS 2048
#define DD 64
#define BH (BB*HH)              // 32
#define ROWS (BH*SS)            // 65536
#define TOT (ROWS*DD)           // 4194304

#define QT 128                  // q rows per CTA
#define KT 64                   // keys per tile
#define NT (SS/KT)              // 32 tiles

// smem row stride in halves: 88 (176 B) -> ldmatrix 8-row phases conflict-free
#define HSTRIDE 88
#define QBYTES  (QT*HSTRIDE*2)      // 22528
#define TBYTES  (KT*HSTRIDE*2)      // 11264
#define WBYTES  (64*HSTRIDE*2)      // 11264

#define SMEM_ATTN (QBYTES + 8*TBYTES)    // 112640 (Q + 4-deep K/V ring) -> exactly 2 CTAs/SM
#define SMEM_PROJ (QBYTES + 3*WBYTES)    // 56320  (x + Wq/Wk/Wv)

// log2(e)/sqrt(64)  (folded into Q at projection time)
#define CEXP 0.18033688011112042f

// fp16 1.0 x2 (B-fragment of all-ones for row-sum MMA)
#define ONES2 0x3C003C00u

// Device scratch for projected Q, K, V (fp16; Q pre-scaled by CEXP)
__device__ __half g_Q[TOT];
__device__ __half g_K[TOT];
__device__ __half g_V[TOT];

// ---------------------------------------------------------------------------
// helpers
// ---------------------------------------------------------------------------
static __device__ __forceinline__ uint32_t smem_u32(const void* p) {
    uint32_t a;
    asm("{ .reg .u64 t; cvta.to.shared.u64 t, %1; cvt.u32.u64 %0, t; }"
        : "=r"(a) : "l"(p));
    return a;
}

static __device__ __forceinline__ void cpa16(uint32_t s, const void* g) {
    asm volatile("cp.async.ca.shared.global [%0], [%1], 16;"
                 :: "r"(s), "l"(g) : "memory");
}

static __device__ __forceinline__ uint32_t packh2(float lo, float hi) {
    __half2 h = __floats2half2_rn(lo, hi);
    return *reinterpret_cast<uint32_t*>(&h);
}

// 2-lane fp16 exp2 on the MUFU pipe (one op for two P values)
static __device__ __forceinline__ uint32_t ex2h2(uint32_t s) {
    uint32_t r;
    asm("ex2.approx.f16x2 %0, %1;" : "=r"(r) : "r"(s));
    return r;
}

#define LDSM_X4(r0, r1, r2, r3, addr) \
    asm volatile("ldmatrix.sync.aligned.m8n8.x4.shared.b16 {%0,%1,%2,%3}, [%4];" \
        : "=r"(r0), "=r"(r1), "=r"(r2), "=r"(r3) : "r"(addr))

#define LDSM_X4_T(r0, r1, r2, r3, addr) \
    asm volatile("ldmatrix.sync.aligned.m8n8.x4.trans.shared.b16 {%0,%1,%2,%3}, [%4];" \
        : "=r"(r0), "=r"(r1), "=r"(r2), "=r"(r3) : "r"(addr))

// c += A (16x16 f16, row) * B (16x8 f16, col), f32 accumulate
static __device__ __forceinline__ void mma16(float c[4], const uint32_t a[4],
                                             uint32_t b0, uint32_t b1) {
    asm volatile(
        "mma.sync.aligned.m16n8k16.row.col.f32.f16.f16.f32 "
        "{%0,%1,%2,%3}, {%4,%5,%6,%7}, {%8,%9}, {%0,%1,%2,%3};"
        : "+f"(c[0]), "+f"(c[1]), "+f"(c[2]), "+f"(c[3])
        : "r"(a[0]), "r"(a[1]), "r"(a[2]), "r"(a[3]), "r"(b0), "r"(b1));
}

// ---------------------------------------------------------------------------
// Kernel 1: fused QKV projection, full fp16 mma.m16n8k16 (proven round 10).
// ---------------------------------------------------------------------------
__global__ __launch_bounds__(128) void proj_f16(
    const float* __restrict__ x,
    const float* __restrict__ Wq, const float* __restrict__ bq,
    const float* __restrict__ Wk, const float* __restrict__ bk,
    const float* __restrict__ Wv, const float* __restrict__ bv)
{
    extern __shared__ char psm[];
    const uint32_t sX = smem_u32(psm);

    const int tid  = threadIdx.x;
    const int warp = tid >> 5;
    const int lane = tid & 31;
    const int mi   = lane >> 3;
    const int jj   = lane & 7;
    const int tig  = lane & 3;
    const int g    = lane >> 2;
    const int rcta = blockIdx.x * 128;

    // ---- stage x (128 x 64 f32 -> f16) ----
    #pragma unroll
    for (int p = 0; p < 16; ++p) {
        const int i = tid + p * 128;
        const int r = i >> 4, seg = i & 15;
        float4 v = *(const float4*)(x + (size_t)(rcta + r) * DD + seg * 4);
        uint2 h = make_uint2(packh2(v.x, v.y), packh2(v.z, v.w));
        *(uint2*)(psm + r * (HSTRIDE*2) + seg * 8) = h;
    }
    // ---- stage W matrices (64 x 64 f32 -> f16 each) ----
    {
        const float* Ws[3] = { Wq, Wk, Wv };
        #pragma unroll
        for (int mat = 0; mat < 3; ++mat) {
            char* wd = psm + QBYTES + mat * WBYTES;
            #pragma unroll
            for (int p = 0; p < 8; ++p) {
                const int i = tid + p * 128;
                const int r = i >> 4, seg = i & 15;
                float4 v = *(const float4*)(Ws[mat] + (size_t)r * DD + seg * 4);
                uint2 h = make_uint2(packh2(v.x, v.y), packh2(v.z, v.w));
                *(uint2*)(wd + r * (HSTRIDE*2) + seg * 8) = h;
            }
        }
    }
    __syncthreads();

    // ---- x A-fragments: 2 m-tiles x 4 k16-chunks ----
    uint32_t xa[2][4][4];
    #pragma unroll
    for (int m = 0; m < 2; ++m)
        #pragma unroll
        for (int kk = 0; kk < 4; ++kk) {
            const uint32_t a = sX +
                ((warp*32 + m*16 + (mi & 1)*8 + jj) * HSTRIDE + kk*16 + (mi >> 1)*8) * 2;
            LDSM_X4(xa[m][kk][0], xa[m][kk][1], xa[m][kk][2], xa[m][kk][3], a);
        }

    const float* bs[3] = { bq, bk, bv };
    __half* outs[3]    = { g_Q, g_K, g_V };

    #pragma unroll
    for (int mat = 0; mat < 3; ++mat) {
        const float* b = bs[mat];
        const uint32_t sW = sX + QBYTES + mat * WBYTES;

        float cacc[2][8][4];
        #pragma unroll
        for (int n = 0; n < 8; ++n) {
            const float b0 = b[n * 8 + 2 * tig];
            const float b1 = b[n * 8 + 2 * tig + 1];
            #pragma unroll
            for (int m = 0; m < 2; ++m) {
                cacc[m][n][0] = b0; cacc[m][n][1] = b1;
                cacc[m][n][2] = b0; cacc[m][n][3] = b1;
            }
        }

        #pragma unroll
        for (int n = 0; n < 8; n += 2) {
            uint32_t wb[2][4][2];
            #pragma unroll
            for (int nn = 0; nn < 2; ++nn)
                #pragma unroll
                for (int kp = 0; kp < 2; ++kp) {
                    const uint32_t a = sW +
                        (((n+nn)*8 + jj) * HSTRIDE + kp*32 + (mi & 1)*8 + (mi >> 1)*16) * 2;
                    LDSM_X4(wb[nn][2*kp][0], wb[nn][2*kp][1],
                            wb[nn][2*kp+1][0], wb[nn][2*kp+1][1], a);
                }
            #pragma unroll
            for (int kk = 0; kk < 4; ++kk)
                #pragma unroll
                for (int nn = 0; nn < 2; ++nn) {
                    mma16(cacc[0][n+nn], xa[0][kk], wb[nn][kk][0], wb[nn][kk][1]);
                    mma16(cacc[1][n+nn], xa[1][kk], wb[nn][kk][0], wb[nn][kk][1]);
                }
        }

        const float scale = (mat == 0) ? CEXP : 1.0f;
        __half* ob = outs[mat] + (size_t)rcta * DD;
        #pragma unroll
        for (int m = 0; m < 2; ++m) {
            const int r0 = warp * 32 + m * 16 + g;
            #pragma unroll
            for (int n = 0; n < 8; ++n) {
                const int c = n * 8 + 2 * tig;
                *(__half2*)(ob + (size_t)(r0    ) * DD + c) =
                    __floats2half2_rn(cacc[m][n][0] * scale, cacc[m][n][1] * scale);
                *(__half2*)(ob + (size_t)(r0 + 8) * DD + c) =
                    __floats2half2_rn(cacc[m][n][2] * scale, cacc[m][n][3] * scale);
            }
        }
    }
}

// ---------------------------------------------------------------------------
// Kernel 2: fp16 mma flash attention, no-max softmax.
// Round-11 chassis: block 128, 2 m-tiles/warp, 4-deep K/V ring (112.6 KB smem
// pins occupancy at exactly 2 CTAs/SM -> best wave quantization), ONE
// __syncthreads per tile, prefetch j+2.
// Round-13's sound piece folded in: per-n-pair exp/pack — each 16-key score
// sliver is ex2.f16x2'd right after its S-MMAs, so pair p's MUFU work
// overlaps pair p+1's tensor work and only 16 sacc regs are ever live.
// ---------------------------------------------------------------------------
__global__ __launch_bounds__(128) void attn_tc(float* __restrict__ out)
{
    extern __shared__ char smc[];
    const uint32_t sQ = smem_u32(smc);
    uint32_t bufK[4], bufV[4];
    #pragma unroll
    for (int i = 0; i < 4; ++i) {
        bufK[i] = sQ + QBYTES + (uint32_t)(2*i) * TBYTES;
        bufV[i] = bufK[i] + TBYTES;
    }

    const int tid  = threadIdx.x;
    const int warp = tid >> 5;
    const int lane = tid & 31;
    const int mi   = lane >> 3;
    const int jj   = lane & 7;
    const int g    = lane >> 2;
    const int tig  = lane & 3;
    const int bh   = blockIdx.y;
    const int q0   = blockIdx.x * QT;
    const size_t rowbase = (size_t)bh * SS;

    const __half* gQ = g_Q + (rowbase + q0) * DD;
    const __half* gK = g_K + rowbase * DD;
    const __half* gV = g_V + rowbase * DD;

    auto prefetch = [&](int j) {
        if (j < NT) {
            const __half* pk = gK + (size_t)j * KT * DD;
            const __half* pv = gV + (size_t)j * KT * DD;
            const uint32_t sk = bufK[j & 3];
            const uint32_t sv = bufV[j & 3];
            #pragma unroll
            for (int p = 0; p < 4; ++p) {
                const int i = tid + p * 128;
                const int r = i >> 3, seg = i & 7;
                const uint32_t so = (uint32_t)(r * (HSTRIDE*2) + seg * 16);
                cpa16(sk + so, pk + r * DD + seg * 8);
                cpa16(sv + so, pv + r * DD + seg * 8);
            }
        }
        asm volatile("cp.async.commit_group;" ::: "memory");
    };

    prefetch(0);
    prefetch(1);

    // ---- stage Q tile ----
    #pragma unroll
    for (int p = 0; p < 8; ++p) {
        const int i = tid + p * 128;
        const int r = i >> 3, seg = i & 7;
        uint4 v = *(const uint4*)(gQ + r * DD + seg * 8);
        *(uint4*)(smc + r * (HSTRIDE*2) + seg * 16) = v;
    }
    __syncthreads();

    // ---- Q A-fragments ----
    uint32_t qf[2][4][4];
    #pragma unroll
    for (int m = 0; m < 2; ++m)
        #pragma unroll
        for (int kk = 0; kk < 4; ++kk) {
            const uint32_t a = sQ +
                ((warp*32 + m*16 + (mi & 1)*8 + jj) * HSTRIDE + kk*16 + (mi >> 1)*8) * 2;
            LDSM_X4(qf[m][kk][0], qf[m][kk][1], qf[m][kk][2], qf[m][kk][3], a);
        }

    float oacc[2][8][4];
    #pragma unroll
    for (int m = 0; m < 2; ++m)
        #pragma unroll
        for (int n = 0; n < 8; ++n)
            #pragma unroll
            for (int e = 0; e < 4; ++e) oacc[m][n][e] = 0.f;
    float lacc[2][4];
    #pragma unroll
    for (int m = 0; m < 2; ++m)
        #pragma unroll
        for (int e = 0; e < 4; ++e) lacc[m][e] = 0.f;

    for (int j = 0; j < NT; ++j) {
        asm volatile("cp.async.wait_group 1;" ::: "memory");
        __syncthreads();
        prefetch(j + 2);   // 4-deep ring: target buffer last read at tile j-2

        const uint32_t K = bufK[j & 3];
        const uint32_t V = bufV[j & 3];

        // ---- S = Q K^T, exp+pack fused per n-pair (16-reg score sliver) ----
        uint32_t pa[2][4][4];
        #pragma unroll
        for (int n = 0; n < 8; n += 2) {
            uint32_t kb[2][4][2];
            #pragma unroll
            for (int nn = 0; nn < 2; ++nn)
                #pragma unroll
                for (int kp = 0; kp < 2; ++kp) {
                    const uint32_t a = K +
                        (((n+nn)*8 + jj) * HSTRIDE + kp*32 + (mi & 1)*8 + (mi >> 1)*16) * 2;
                    LDSM_X4(kb[nn][2*kp][0], kb[nn][2*kp][1],
                            kb[nn][2*kp+1][0], kb[nn][2*kp+1][1], a);
                }

            float sp[2][2][4];
            #pragma unroll
            for (int m = 0; m < 2; ++m)
                #pragma unroll
                for (int nn = 0; nn < 2; ++nn)
                    #pragma unroll
                    for (int e = 0; e < 4; ++e) sp[m][nn][e] = 0.f;

            #pragma unroll
            for (int kk = 0; kk < 4; ++kk)
                #pragma unroll
                for (int nn = 0; nn < 2; ++nn) {
                    mma16(sp[0][nn], qf[0][kk], kb[nn][kk][0], kb[nn][kk][1]);
                    mma16(sp[1][nn], qf[1][kk], kb[nn][kk][0], kb[nn][kk][1]);
                }

            const int pr = n >> 1;
            #pragma unroll
            for (int m = 0; m < 2; ++m) {
                pa[m][pr][0] = ex2h2(packh2(sp[m][0][0], sp[m][0][1]));
                pa[m][pr][1] = ex2h2(packh2(sp[m][0][2], sp[m][0][3]));
                pa[m][pr][2] = ex2h2(packh2(sp[m][1][0], sp[m][1][1]));
                pa[m][pr][3] = ex2h2(packh2(sp[m][1][2], sp[m][1][3]));
            }
        }

        // ---- row sums via all-ones B fragment ----
        #pragma unroll
        for (int m = 0; m < 2; ++m)
            #pragma unroll
            for (int kk = 0; kk < 4; ++kk)
                mma16(lacc[m], pa[m][kk], ONES2, ONES2);

        // ---- O += P V ----
        #pragma unroll
        for (int n = 0; n < 8; n += 2) {
            uint32_t vb[2][4][2];
            #pragma unroll
            for (int nn = 0; nn < 2; ++nn)
                #pragma unroll
                for (int kp = 0; kp < 2; ++kp) {
                    const uint32_t a = V +
                        ((kp*32 + (mi >> 1)*16 + (mi & 1)*8 + jj) * HSTRIDE + (n+nn)*8) * 2;
                    LDSM_X4_T(vb[nn][2*kp][0], vb[nn][2*kp][1],
                              vb[nn][2*kp+1][0], vb[nn][2*kp+1][1], a);
                }
            #pragma unroll
            for (int kk = 0; kk < 4; ++kk)
                #pragma unroll
                for (int nn = 0; nn < 2; ++nn) {
                    mma16(oacc[0][n+nn], pa[0][kk], vb[nn][kk][0], vb[nn][kk][1]);
                    mma16(oacc[1][n+nn], pa[1][kk], vb[nn][kk][0], vb[nn][kk][1]);
                }
        }
    }

    // ---- epilogue: normalize and store (lacc[m][0]=rows g, [2]=rows g+8) ----
    float inv[2][2];
    #pragma unroll
    for (int m = 0; m < 2; ++m) {
        inv[m][0] = 1.f / lacc[m][0];
        inv[m][1] = 1.f / lacc[m][2];
    }

    float* ob = out + (rowbase + q0 + warp * 32) * DD;
    #pragma unroll
    for (int m = 0; m < 2; ++m) {
        const int r0 = m * 16 + g;
        #pragma unroll
        for (int n = 0; n < 8; ++n) {
            const int c = n * 8 + 2 * tig;
            float2 v0 = make_float2(oacc[m][n][0] * inv[m][0], oacc[m][n][1] * inv[m][0]);
            *(float2*)(ob + r0 * DD + c) = v0;
            float2 v1 = make_float2(oacc[m][n][2] * inv[m][1], oacc[m][n][3] * inv[m][1]);
            *(float2*)(ob + (r0 + 8) * DD + c) = v1;
        }
    }
}

// ---------------------------------------------------------------------------
extern "C" void kernel_launch(void* const* d_in, const int* in_sizes, int n_in,
                              void* d_out, int out_size)
{
    const float* x  = (const float*)d_in[0];
    const float* Wq = (const float*)d_in[1];
    const float* bq = (const float*)d_in[2];
    const float* Wk = (const float*)d_in[3];
    const float* bk = (const float*)d_in[4];
    const float* Wv = (const float*)d_in[5];
    const float* bv = (const float*)d_in[6];
    float* out = (float*)d_out;

    static int configured = 0;
    if (!configured) {
        cudaFuncSetAttribute(attn_tc, cudaFuncAttributeMaxDynamicSharedMemorySize, SMEM_ATTN);
        cudaFuncSetAttribute(proj_f16, cudaFuncAttributeMaxDynamicSharedMemorySize, SMEM_PROJ);
        configured = 1;
    }

    proj_f16<<<ROWS / 128, 128, SMEM_PROJ>>>(x, Wq, bq, Wk, bk, Wv, bv);

    dim3 agrid(SS / QT, BH);
    attn_tc<<<agrid, 128, SMEM_ATTN>>>(out);
}